// round 2
// baseline (speedup 1.0000x reference)
#include <cuda_runtime.h>
#include <cuda_bf16.h>
#include <math.h>

// Problem constants
#define Bc     8
#define Tc     2048
#define DMc    1024
#define Hc     8
#define SDc    64
#define INNERc 512
#define HIDc   4096
#define Mrows  (Bc * Tc)   // 16384

// ---------------- device scratch (allocation-free rule: __device__ globals) ----
__device__ float g_n  [(size_t)Mrows * DMc];     // LN(x)
__device__ float g_pa [(size_t)Mrows * INNERc];  // tanh(n@Wa)
__device__ float g_pb [(size_t)Mrows * INNERc];
__device__ float g_pql[(size_t)Mrows * INNERc];
__device__ float g_pqr[(size_t)Mrows * INNERc];
__device__ float g_sd [(size_t)Mrows * Hc];
__device__ float g_pd [(size_t)Mrows * Hc];
__device__ float g_ys [(size_t)Mrows * INNERc];  // scan output
__device__ float g_h  [(size_t)Mrows * DMc];     // x + mixed
__device__ float g_fin[(size_t)Mrows * DMc];     // LN(h)
__device__ float g_mid[(size_t)Mrows * HIDc];    // gelu(ffn_in@W1+b1)

// ---------------- LayerNorm: one block per row of 1024 --------------------------
__global__ void ln_kernel(const float* __restrict__ X,
                          const float* __restrict__ gam,
                          const float* __restrict__ bet,
                          float* __restrict__ Out)
{
    int row = blockIdx.x;
    int tid = threadIdx.x;               // 256 threads, 4 floats each
    const float4* xr = reinterpret_cast<const float4*>(X + (size_t)row * DMc);
    float4 v = xr[tid];
    float s = v.x + v.y + v.z + v.w;
    float q = v.x * v.x + v.y * v.y + v.z * v.z + v.w * v.w;
    int lane = tid & 31, wid = tid >> 5;
#pragma unroll
    for (int o = 16; o; o >>= 1) {
        s += __shfl_xor_sync(0xffffffffu, s, o);
        q += __shfl_xor_sync(0xffffffffu, q, o);
    }
    __shared__ float rs[8], rq[8];
    if (!lane) { rs[wid] = s; rq[wid] = q; }
    __syncthreads();
    if (tid == 0) {
        float S = 0.f, Q = 0.f;
#pragma unroll
        for (int i = 0; i < 8; i++) { S += rs[i]; Q += rq[i]; }
        rs[0] = S; rq[0] = Q;
    }
    __syncthreads();
    float mu  = rs[0] * (1.0f / DMc);
    float var = rq[0] * (1.0f / DMc) - mu * mu;
    float rstd = rsqrtf(var + 1e-5f);
    const float4 gg = reinterpret_cast<const float4*>(gam)[tid];
    const float4 bb = reinterpret_cast<const float4*>(bet)[tid];
    float4 o;
    o.x = (v.x - mu) * rstd * gg.x + bb.x;
    o.y = (v.y - mu) * rstd * gg.y + bb.y;
    o.z = (v.z - mu) * rstd * gg.z + bb.z;
    o.w = (v.w - mu) * rstd * gg.w + bb.w;
    reinterpret_cast<float4*>(Out + (size_t)row * DMc)[tid] = o;
}

// ---------------- Tiled SGEMM with fused epilogues --------------------------
// C[M,N] = epi(A[M,K] @ W[K,N]); BM=128, BN=64, BK=16, 256 thr, 8x4 per thread
enum { EPI_TANH = 1, EPI_RES = 2, EPI_GELU_BIAS = 3, EPI_RES_BIAS = 4 };

template <int EPI>
__global__ __launch_bounds__(256)
void sgemm_kernel(const float* __restrict__ A, const float* __restrict__ W,
                  float* __restrict__ C, int M, int N, int K,
                  const float* __restrict__ res, const float* __restrict__ bias)
{
    const int BM = 128, BN = 64, BK = 16;
    __shared__ float As[BK][BM + 4];   // +4 pad to soften store conflicts
    __shared__ float Bs[BK][BN];

    int tid = threadIdx.x;
    int bm = blockIdx.y * BM;
    int bn = blockIdx.x * BN;
    int tx = tid & 15, ty = tid >> 4;
    int row0 = ty * 8, col0 = tx * 4;

    float acc[8][4];
#pragma unroll
    for (int i = 0; i < 8; i++)
#pragma unroll
        for (int j = 0; j < 4; j++) acc[i][j] = 0.f;

    int arow0 = tid >> 2;                 // 0..63 (+64 for second half)
    int ac4   = (tid & 3) * 4;            // 0,4,8,12
    int brow  = tid >> 4;                 // 0..15
    int bc4   = (tid & 15) * 4;           // 0..60

    for (int k0 = 0; k0 < K; k0 += BK) {
#pragma unroll
        for (int r = 0; r < 2; ++r) {
            int arow = arow0 + r * 64;
            float4 v = *reinterpret_cast<const float4*>(
                &A[(size_t)(bm + arow) * K + k0 + ac4]);
            As[ac4 + 0][arow] = v.x;
            As[ac4 + 1][arow] = v.y;
            As[ac4 + 2][arow] = v.z;
            As[ac4 + 3][arow] = v.w;
        }
        float4 bv = *reinterpret_cast<const float4*>(
            &W[(size_t)(k0 + brow) * N + bn + bc4]);
        *reinterpret_cast<float4*>(&Bs[brow][bc4]) = bv;
        __syncthreads();

#pragma unroll
        for (int kk = 0; kk < BK; ++kk) {
            float4 a0 = *reinterpret_cast<const float4*>(&As[kk][row0]);
            float4 a1 = *reinterpret_cast<const float4*>(&As[kk][row0 + 4]);
            float4 b0 = *reinterpret_cast<const float4*>(&Bs[kk][col0]);
            float ra[8] = {a0.x, a0.y, a0.z, a0.w, a1.x, a1.y, a1.z, a1.w};
            float rb[4] = {b0.x, b0.y, b0.z, b0.w};
#pragma unroll
            for (int i = 0; i < 8; i++)
#pragma unroll
                for (int j = 0; j < 4; j++) acc[i][j] += ra[i] * rb[j];
        }
        __syncthreads();
    }

    // epilogue, vectorized over the 4 contiguous columns
    float4 bv4;
    if (EPI == EPI_GELU_BIAS || EPI == EPI_RES_BIAS)
        bv4 = *reinterpret_cast<const float4*>(&bias[bn + col0]);
#pragma unroll
    for (int i = 0; i < 8; i++) {
        int m = bm + row0 + i;
        size_t off = (size_t)m * N + bn + col0;
        float v0 = acc[i][0], v1 = acc[i][1], v2 = acc[i][2], v3 = acc[i][3];
        if (EPI == EPI_TANH) {
            v0 = tanhf(v0); v1 = tanhf(v1); v2 = tanhf(v2); v3 = tanhf(v3);
        } else if (EPI == EPI_GELU_BIAS) {
            v0 += bv4.x; v1 += bv4.y; v2 += bv4.z; v3 += bv4.w;
            const float is2 = 0.70710678118654752f;
            v0 = 0.5f * v0 * (1.f + erff(v0 * is2));
            v1 = 0.5f * v1 * (1.f + erff(v1 * is2));
            v2 = 0.5f * v2 * (1.f + erff(v2 * is2));
            v3 = 0.5f * v3 * (1.f + erff(v3 * is2));
        } else if (EPI == EPI_RES) {
            float4 r4 = *reinterpret_cast<const float4*>(&res[off]);
            v0 += r4.x; v1 += r4.y; v2 += r4.z; v3 += r4.w;
        } else if (EPI == EPI_RES_BIAS) {
            float4 r4 = *reinterpret_cast<const float4*>(&res[off]);
            v0 += bv4.x + r4.x; v1 += bv4.y + r4.y;
            v2 += bv4.z + r4.z; v3 += bv4.w + r4.w;
        }
        float4 o = make_float4(v0, v1, v2, v3);
        *reinterpret_cast<float4*>(&C[off]) = o;
    }
}

// ---------------- sd/pd: narrow GEMM (N=8+8) + sigmoid ----------------------
__global__ __launch_bounds__(256)
void sdpd_kernel(const float* __restrict__ Nmat,
                 const float* __restrict__ Wsd, const float* __restrict__ bsd,
                 const float* __restrict__ Wpd, const float* __restrict__ bpd,
                 float* __restrict__ SDo, float* __restrict__ PDo)
{
    const int RB = 128;
    __shared__ float As[16][RB];
    __shared__ float Ws[16][16];          // cols 0-7: Wsd, 8-15: Wpd
    int tid = threadIdx.x;
    int row = tid & 127;
    int cg  = tid >> 7;                   // 0 -> sd, 1 -> pd
    int m0  = blockIdx.x * RB;

    float acc[8];
#pragma unroll
    for (int j = 0; j < 8; j++) acc[j] = 0.f;

    int wk = tid >> 4;                    // 0..15
    int wc = tid & 15;                    // 0..15

    for (int k0 = 0; k0 < DMc; k0 += 16) {
#pragma unroll
        for (int r = 0; r < 2; ++r) {
            int idx = tid + r * 256;
            int ar = idx >> 2;
            int c4 = (idx & 3) * 4;
            float4 v = *reinterpret_cast<const float4*>(
                &Nmat[(size_t)(m0 + ar) * DMc + k0 + c4]);
            As[c4 + 0][ar] = v.x;
            As[c4 + 1][ar] = v.y;
            As[c4 + 2][ar] = v.z;
            As[c4 + 3][ar] = v.w;
        }
        Ws[wk][wc] = (wc < 8) ? Wsd[(size_t)(k0 + wk) * Hc + wc]
                              : Wpd[(size_t)(k0 + wk) * Hc + (wc - 8)];
        __syncthreads();
#pragma unroll
        for (int kk = 0; kk < 16; ++kk) {
            float a = As[kk][row];
#pragma unroll
            for (int j = 0; j < 8; j++) acc[j] += a * Ws[kk][cg * 8 + j];
        }
        __syncthreads();
    }
    float* outp = cg ? PDo : SDo;
    const float* bp = cg ? bpd : bsd;
#pragma unroll
    for (int j = 0; j < 8; j++) {
        float v = acc[j] + bp[j];
        outp[(size_t)(m0 + row) * Hc + j] = 1.0f / (1.0f + expf(-v));
    }
}

// ---------------- recurrent scan over T ------------------------------------
// grid: B*H*2 blocks (e split in halves of 32); 256 threads.
// thread owns pair[d0..d0+7][e], pair in registers; state double-buffered in SMEM;
// next step's (a,b,ql,qr,sd,pd) prefetched into registers during compute.
__global__ __launch_bounds__(256)
void scan_kernel(const float* __restrict__ Av, const float* __restrict__ Bv,
                 const float* __restrict__ QL, const float* __restrict__ QR,
                 const float* __restrict__ SDg, const float* __restrict__ PDg,
                 float* __restrict__ Y)
{
    int blk = blockIdx.x;
    int es = blk & 1;
    int h  = (blk >> 1) & 7;
    int b  = blk >> 4;
    int e_base = es * 32;

    int tid = threadIdx.x;
    int e_local = tid & 31;
    int dg = tid >> 5;        // 0..7
    int d0 = dg * 8;

    __shared__ float s_vec[4][64];     // a, b, ql, qr
    __shared__ float s_state[2][64];
    __shared__ float s_red[8][32];
    __shared__ float s_sp[2];          // sd, pd

    float pair[8];
#pragma unroll
    for (int i = 0; i < 8; i++) pair[i] = 0.f;
    if (tid < 64) { s_state[0][tid] = 0.f; s_state[1][tid] = 0.f; }

    int grp = tid >> 6;       // which vector this thread prefetches
    int lane64 = tid & 63;
    const float* myptr = (grp == 0) ? Av : (grp == 1) ? Bv : (grp == 2) ? QL : QR;

    size_t rowbase = ((size_t)b * Tc) * INNERc + (size_t)h * SDc;
    size_t sp_base = ((size_t)b * Tc) * Hc + h;

    float pf = myptr[rowbase + lane64];
    float pf_sd = 0.f, pf_pd = 0.f;
    if (tid == 0) { pf_sd = SDg[sp_base]; pf_pd = PDg[sp_base]; }

    for (int t = 0; t < Tc; ++t) {
        int p = t & 1;
        // publish prefetched vectors for step t
        s_vec[grp][lane64] = pf;
        if (tid == 0) { s_sp[0] = pf_sd; s_sp[1] = pf_pd; }
        __syncthreads();                               // sync A

        // prefetch step t+1 (latency hidden behind compute)
        if (t + 1 < Tc) {
            pf = myptr[rowbase + (size_t)(t + 1) * INNERc + lane64];
            if (tid == 0) {
                size_t sb = sp_base + (size_t)(t + 1) * Hc;
                pf_sd = SDg[sb]; pf_pd = PDg[sb];
            }
        }

        float sdv = s_sp[0], pdv = s_sp[1];
        float be = s_vec[1][e_base + e_local];
        float ompd_be = (1.f - pdv) * be;
        float qrv = s_vec[3][e_base + e_local];        // read BEFORE sync B
        float acc = 0.f;
#pragma unroll
        for (int i = 0; i < 8; i++) {
            int d = d0 + i;
            float ps = s_state[p][d];
            pair[i] = pdv * pair[i] + ompd_be * ps;
            acc += pair[i] * s_vec[2][d];
        }
        s_red[dg][e_local] = acc;
        if (tid < 64) {   // state update into the other buffer (no WAR)
            s_state[p ^ 1][tid] = sdv * s_state[p][tid] + (1.f - sdv) * s_vec[0][tid];
        }
        __syncthreads();                               // sync B
        if (dg == 0) {
            float left = 0.f;
#pragma unroll
            for (int g2 = 0; g2 < 8; ++g2) left += s_red[g2][e_local];
            Y[rowbase + (size_t)t * INNERc + e_base + e_local] = left * qrv;
        }
    }
}

// ---------------- launch ----------------------------------------------------
static float* sym(const void* s)
{
    void* p = nullptr;
    cudaGetSymbolAddress(&p, s);
    return (float*)p;
}

extern "C" void kernel_launch(void* const* d_in, const int* in_sizes, int n_in,
                              void* d_out, int out_size)
{
    const float* x    = (const float*)d_in[0];
    const float* ln_g = (const float*)d_in[1];
    const float* ln_b = (const float*)d_in[2];
    const float* ffn_g= (const float*)d_in[3];
    const float* ffn_b= (const float*)d_in[4];
    const float* Wa   = (const float*)d_in[5];
    const float* Wb   = (const float*)d_in[6];
    const float* Wql  = (const float*)d_in[7];
    const float* Wqr  = (const float*)d_in[8];
    const float* Wsd  = (const float*)d_in[9];
    const float* bsd  = (const float*)d_in[10];
    const float* Wpd  = (const float*)d_in[11];
    const float* bpd  = (const float*)d_in[12];
    const float* Wout = (const float*)d_in[13];
    const float* W1   = (const float*)d_in[14];
    const float* b1   = (const float*)d_in[15];
    const float* W2   = (const float*)d_in[16];
    const float* b2   = (const float*)d_in[17];
    float* out = (float*)d_out;

    float* n_   = sym(g_n);
    float* pa   = sym(g_pa);
    float* pb   = sym(g_pb);
    float* pql  = sym(g_pql);
    float* pqr  = sym(g_pqr);
    float* sdp  = sym(g_sd);
    float* pdp  = sym(g_pd);
    float* ys   = sym(g_ys);
    float* hbuf = sym(g_h);
    float* fin  = sym(g_fin);
    float* mid  = sym(g_mid);

    // 1. n = LN(x)
    ln_kernel<<<Mrows, 256>>>(x, ln_g, ln_b, n_);

    // 2. projections: tanh(n @ W*)   [16384 x 1024] x [1024 x 512]
    {
        dim3 grid(INNERc / 64, Mrows / 128);
        sgemm_kernel<EPI_TANH><<<grid, 256>>>(n_, Wa,  pa,  Mrows, INNERc, DMc, nullptr, nullptr);
        sgemm_kernel<EPI_TANH><<<grid, 256>>>(n_, Wb,  pb,  Mrows, INNERc, DMc, nullptr, nullptr);
        sgemm_kernel<EPI_TANH><<<grid, 256>>>(n_, Wql, pql, Mrows, INNERc, DMc, nullptr, nullptr);
        sgemm_kernel<EPI_TANH><<<grid, 256>>>(n_, Wqr, pqr, Mrows, INNERc, DMc, nullptr, nullptr);
    }

    // 3. sd/pd gates
    sdpd_kernel<<<Mrows / 128, 256>>>(n_, Wsd, bsd, Wpd, bpd, sdp, pdp);

    // 4. recurrent scan -> ys
    scan_kernel<<<Bc * Hc * 2, 256>>>(pa, pb, pql, pqr, sdp, pdp, ys);

    // 5. h = x + ys @ Wout   [16384 x 512] x [512 x 1024]
    {
        dim3 grid(DMc / 64, Mrows / 128);
        sgemm_kernel<EPI_RES><<<grid, 256>>>(ys, Wout, hbuf, Mrows, DMc, INNERc, x, nullptr);
    }

    // 6. ffn_in = LN(h)
    ln_kernel<<<Mrows, 256>>>(hbuf, ffn_g, ffn_b, fin);

    // 7. mid = gelu(ffn_in @ W1 + b1)   [16384 x 1024] x [1024 x 4096]
    {
        dim3 grid(HIDc / 64, Mrows / 128);
        sgemm_kernel<EPI_GELU_BIAS><<<grid, 256>>>(fin, W1, mid, Mrows, HIDc, DMc, nullptr, b1);
    }

    // 8. out = h + mid @ W2 + b2   [16384 x 4096] x [4096 x 1024]
    {
        dim3 grid(DMc / 64, Mrows / 128);
        sgemm_kernel<EPI_RES_BIAS><<<grid, 256>>>(mid, W2, out, Mrows, DMc, HIDc, hbuf, b2);
    }
}

// round 4
// speedup vs baseline: 2.6197x; 2.6197x over previous
#include <cuda_runtime.h>
#include <cuda_bf16.h>
#include <math.h>
#include <stdint.h>

#define Bc 8
#define Tc 2048
#define DMc 1024
#define Hc 8
#define SDc 64
#define INNERc 512
#define HIDc 4096
#define Mrows (Bc * Tc)

typedef __nv_bfloat16 bf16;

__device__ __align__(256) float g_n  [(size_t)Mrows * DMc];
__device__ __align__(256) bf16  g_nh [(size_t)Mrows * DMc];
__device__ __align__(256) bf16  g_nl [(size_t)Mrows * DMc];
__device__ __align__(256) float g_pa [(size_t)Mrows * INNERc];
__device__ __align__(256) float g_pb [(size_t)Mrows * INNERc];
__device__ __align__(256) float g_pql[(size_t)Mrows * INNERc];
__device__ __align__(256) float g_pqr[(size_t)Mrows * INNERc];
__device__ __align__(256) float g_sd [(size_t)Mrows * Hc];
__device__ __align__(256) float g_pd [(size_t)Mrows * Hc];
__device__ __align__(256) bf16  g_ysh[(size_t)Mrows * INNERc];
__device__ __align__(256) bf16  g_ysl[(size_t)Mrows * INNERc];
__device__ __align__(256) float g_h  [(size_t)Mrows * DMc];
__device__ __align__(256) bf16  g_finh[(size_t)Mrows * DMc];
__device__ __align__(256) bf16  g_finl[(size_t)Mrows * DMc];
__device__ __align__(256) bf16  g_midh[(size_t)Mrows * HIDc];
__device__ __align__(256) bf16  g_midl[(size_t)Mrows * HIDc];
__device__ __align__(256) bf16 g_wa_h[INNERc*DMc], g_wa_l[INNERc*DMc];
__device__ __align__(256) bf16 g_wb_h[INNERc*DMc], g_wb_l[INNERc*DMc];
__device__ __align__(256) bf16 g_wql_h[INNERc*DMc], g_wql_l[INNERc*DMc];
__device__ __align__(256) bf16 g_wqr_h[INNERc*DMc], g_wqr_l[INNERc*DMc];
__device__ __align__(256) bf16 g_wo_h[DMc*INNERc], g_wo_l[DMc*INNERc];
__device__ __align__(256) bf16 g_w1_h[HIDc*DMc],  g_w1_l[HIDc*DMc];
__device__ __align__(256) bf16 g_w2_h[DMc*HIDc],  g_w2_l[DMc*HIDc];

// ---------------- helpers ----------------
__device__ __forceinline__ uint32_t smem_u32(const void* p) {
    return (uint32_t)__cvta_generic_to_shared(p);
}
__device__ __forceinline__ void cp16(uint32_t dst, const void* src) {
    asm volatile("cp.async.cg.shared.global [%0], [%1], 16;\n" :: "r"(dst), "l"(src));
}
__device__ __forceinline__ void cp_commit() { asm volatile("cp.async.commit_group;\n"); }
template <int NN> __device__ __forceinline__ void cp_wait() {
    asm volatile("cp.async.wait_group %0;\n" :: "n"(NN));
}
__device__ __forceinline__ void ldm_x4(uint32_t* r, uint32_t addr) {
    asm volatile("ldmatrix.sync.aligned.m8n8.x4.shared.b16 {%0,%1,%2,%3}, [%4];"
        : "=r"(r[0]), "=r"(r[1]), "=r"(r[2]), "=r"(r[3]) : "r"(addr));
}
__device__ __forceinline__ void mma_bf16(float* d, const uint32_t* a, const uint32_t* b) {
    asm volatile("mma.sync.aligned.m16n8k16.row.col.f32.bf16.bf16.f32 "
        "{%0,%1,%2,%3},{%4,%5,%6,%7},{%8,%9},{%0,%1,%2,%3};"
        : "+f"(d[0]), "+f"(d[1]), "+f"(d[2]), "+f"(d[3])
        : "r"(a[0]), "r"(a[1]), "r"(a[2]), "r"(a[3]), "r"(b[0]), "r"(b[1]));
}

// ---------------- LN + bf16 hi/lo split ----------------
template <bool F32OUT>
__global__ void ln_split_kernel(const float* __restrict__ X,
                                const float* __restrict__ gam,
                                const float* __restrict__ bet,
                                float* __restrict__ Of,
                                bf16* __restrict__ Oh, bf16* __restrict__ Ol)
{
    int row = blockIdx.x, tid = threadIdx.x;
    const float4* xr = reinterpret_cast<const float4*>(X + (size_t)row * DMc);
    float4 v = xr[tid];
    float s = v.x + v.y + v.z + v.w;
    float q = v.x*v.x + v.y*v.y + v.z*v.z + v.w*v.w;
    int lane = tid & 31, wid = tid >> 5;
#pragma unroll
    for (int o = 16; o; o >>= 1) {
        s += __shfl_xor_sync(0xffffffffu, s, o);
        q += __shfl_xor_sync(0xffffffffu, q, o);
    }
    __shared__ float rs[8], rq[8];
    if (!lane) { rs[wid] = s; rq[wid] = q; }
    __syncthreads();
    if (tid == 0) {
        float S = 0.f, Q = 0.f;
#pragma unroll
        for (int i = 0; i < 8; i++) { S += rs[i]; Q += rq[i]; }
        rs[0] = S; rq[0] = Q;
    }
    __syncthreads();
    float mu = rs[0] * (1.0f / DMc);
    float var = rq[0] * (1.0f / DMc) - mu * mu;
    float rstd = rsqrtf(var + 1e-5f);
    const float4 gg = reinterpret_cast<const float4*>(gam)[tid];
    const float4 bb = reinterpret_cast<const float4*>(bet)[tid];
    float o[4];
    o[0] = (v.x-mu)*rstd*gg.x + bb.x; o[1] = (v.y-mu)*rstd*gg.y + bb.y;
    o[2] = (v.z-mu)*rstd*gg.z + bb.z; o[3] = (v.w-mu)*rstd*gg.w + bb.w;
    size_t off = (size_t)row * DMc + tid * 4;
    if (F32OUT)
        *reinterpret_cast<float4*>(Of + off) = make_float4(o[0], o[1], o[2], o[3]);
    bf16 h[4], l[4];
#pragma unroll
    for (int j = 0; j < 4; j++) {
        h[j] = __float2bfloat16(o[j]);
        l[j] = __float2bfloat16(o[j] - __bfloat162float(h[j]));
    }
    __nv_bfloat162 h0 = __halves2bfloat162(h[0],h[1]), h1 = __halves2bfloat162(h[2],h[3]);
    __nv_bfloat162 l0 = __halves2bfloat162(l[0],l[1]), l1 = __halves2bfloat162(l[2],l[3]);
    *reinterpret_cast<uint2*>(Oh + off) = make_uint2(*(uint32_t*)&h0, *(uint32_t*)&h1);
    *reinterpret_cast<uint2*>(Ol + off) = make_uint2(*(uint32_t*)&l0, *(uint32_t*)&l1);
}

// ---------------- weight transpose+split: W[K,N] f32 -> [N,K] bf16 h/l ------
__global__ void tsplit_kernel(const float* __restrict__ W,
                              bf16* __restrict__ Oh, bf16* __restrict__ Ol,
                              int K, int N)
{
    __shared__ float t[32][33];
    int n0 = blockIdx.x * 32, k0 = blockIdx.y * 32;
    int tx = threadIdx.x, ty = threadIdx.y;  // 32 x 8
#pragma unroll
    for (int j = 0; j < 32; j += 8)
        t[ty + j][tx] = W[(size_t)(k0 + ty + j) * N + n0 + tx];
    __syncthreads();
#pragma unroll
    for (int j = 0; j < 32; j += 8) {
        float v = t[tx][ty + j];
        bf16 h = __float2bfloat16(v);
        size_t o = (size_t)(n0 + ty + j) * K + k0 + tx;
        Oh[o] = h; Ol[o] = __float2bfloat16(v - __bfloat162float(h));
    }
}

// ---------------- mma.sync split-bf16 GEMM: tile 128x128x32 ------------------
// A=[M,K] bf16 h/l row-major; B=[N,K] bf16 h/l row-major (=col-major KxN).
enum { EPI_TANH = 1, EPI_RES = 2, EPI_GELU = 3, EPI_RES_BIAS = 4 };
#define LDB 80u            // smem row stride in bytes (32 bf16 + 8 pad)
#define MATB 10240u        // 128 rows * 80B
#define STAGEB 40960u      // Ah|Al|Bh|Bl
#define SMEM_DYN (2 * 40960)

template <int EPI>
__global__ __launch_bounds__(256)
void mma_gemm(const bf16* __restrict__ Ah, const bf16* __restrict__ Al,
              const bf16* __restrict__ Bh, const bf16* __restrict__ Bl,
              float* __restrict__ C, bf16* __restrict__ Oh, bf16* __restrict__ Ol,
              const float* __restrict__ res, const float* __restrict__ bias,
              int M, int N, int K)
{
    extern __shared__ char smraw[];
    uint32_t sbase = smem_u32(smraw);
    int tid = threadIdx.x, lane = tid & 31, wid = tid >> 5;
    int warp_m = wid & 3, warp_n = wid >> 2;
    int bm = blockIdx.y * 128, bn = blockIdx.x * 128;

    float acc[2][8][4];
#pragma unroll
    for (int a = 0; a < 2; a++)
#pragma unroll
        for (int b = 0; b < 8; b++)
#pragma unroll
            for (int c = 0; c < 4; c++) acc[a][b][c] = 0.f;

    auto load_stage = [&](int c) {
        int k0 = c * 32;
        uint32_t st = sbase + (uint32_t)(c & 1) * STAGEB;
#pragma unroll
        for (int i = 0; i < 8; i++) {
            int id = tid + i * 256;
            int mat = id >> 9, rem = id & 511;
            int r = rem >> 2, g = rem & 3;
            const bf16* src = (mat == 0) ? Ah : (mat == 1) ? Al : (mat == 2) ? Bh : Bl;
            int row = ((mat < 2) ? bm : bn) + r;
            cp16(st + (uint32_t)mat * MATB + (uint32_t)r * LDB + (uint32_t)g * 16u,
                 src + (size_t)row * K + k0 + g * 8);
        }
        cp_commit();
    };

    int NC = K / 32;
    load_stage(0);
    load_stage(1);

    // per-thread ldmatrix smem addresses (offsets within a stage)
    uint32_t a_off = (uint32_t)(warp_m * 32 + (lane & 15)) * LDB + (uint32_t)((lane >> 4) << 4);
    int bg = lane >> 3, bt = lane & 7;
    uint32_t b_off = (uint32_t)(warp_n * 64 + ((bg >> 1) << 3) + bt) * LDB + (uint32_t)((bg & 1) << 4);

    for (int c = 0; c < NC; c++) {
        cp_wait<1>();
        __syncthreads();
        uint32_t st = sbase + (uint32_t)(c & 1) * STAGEB;
#pragma unroll
        for (int ks = 0; ks < 2; ks++) {
            uint32_t koff = (uint32_t)(ks << 5);   // 16 bf16 = 32 bytes
            uint32_t ah[2][4], al[2][4];
#pragma unroll
            for (int mt = 0; mt < 2; mt++) {
                uint32_t ad = st + a_off + (uint32_t)(mt * 16) * LDB + koff;
                ldm_x4(ah[mt], ad);
                ldm_x4(al[mt], ad + MATB);
            }
            uint32_t bh[8][2], bl[8][2];
#pragma unroll
            for (int jj = 0; jj < 4; jj++) {
                uint32_t bd = st + 2 * MATB + b_off + (uint32_t)(jj * 16) * LDB + koff;
                uint32_t r4[4];
                ldm_x4(r4, bd);
                bh[jj*2][0] = r4[0]; bh[jj*2][1] = r4[1];
                bh[jj*2+1][0] = r4[2]; bh[jj*2+1][1] = r4[3];
                ldm_x4(r4, bd + MATB);
                bl[jj*2][0] = r4[0]; bl[jj*2][1] = r4[1];
                bl[jj*2+1][0] = r4[2]; bl[jj*2+1][1] = r4[3];
            }
#pragma unroll
            for (int mt = 0; mt < 2; mt++)
#pragma unroll
                for (int nt = 0; nt < 8; nt++) {
                    mma_bf16(acc[mt][nt], ah[mt], bh[nt]);
                    mma_bf16(acc[mt][nt], ah[mt], bl[nt]);
                    mma_bf16(acc[mt][nt], al[mt], bh[nt]);
                }
        }
        __syncthreads();
        if (c + 2 < NC) load_stage(c + 2);
    }

    // ---- epilogue ----
#pragma unroll
    for (int mt = 0; mt < 2; mt++)
#pragma unroll
        for (int nt = 0; nt < 8; nt++) {
            int col = bn + warp_n * 64 + nt * 8 + (lane & 3) * 2;
            int r0 = bm + warp_m * 32 + mt * 16 + (lane >> 2);
#pragma unroll
            for (int hr = 0; hr < 2; hr++) {
                int m = r0 + hr * 8;
                float v0 = acc[mt][nt][hr*2+0], v1 = acc[mt][nt][hr*2+1];
                size_t off = (size_t)m * N + col;
                if (EPI == EPI_GELU) {
                    float2 bb = *reinterpret_cast<const float2*>(&bias[col]);
                    v0 += bb.x; v1 += bb.y;
                    const float is2 = 0.70710678118654752f;
                    v0 = 0.5f * v0 * (1.f + erff(v0 * is2));
                    v1 = 0.5f * v1 * (1.f + erff(v1 * is2));
                    bf16 h0 = __float2bfloat16(v0), h1 = __float2bfloat16(v1);
                    bf16 l0 = __float2bfloat16(v0 - __bfloat162float(h0));
                    bf16 l1 = __float2bfloat16(v1 - __bfloat162float(h1));
                    __nv_bfloat162 hh = __halves2bfloat162(h0, h1);
                    __nv_bfloat162 ll = __halves2bfloat162(l0, l1);
                    *reinterpret_cast<uint32_t*>(&Oh[off]) = *(uint32_t*)&hh;
                    *reinterpret_cast<uint32_t*>(&Ol[off]) = *(uint32_t*)&ll;
                } else {
                    if (EPI == EPI_TANH) { v0 = tanhf(v0); v1 = tanhf(v1); }
                    else if (EPI == EPI_RES) {
                        float2 rr = *reinterpret_cast<const float2*>(&res[off]);
                        v0 += rr.x; v1 += rr.y;
                    } else if (EPI == EPI_RES_BIAS) {
                        float2 rr = *reinterpret_cast<const float2*>(&res[off]);
                        float2 bb = *reinterpret_cast<const float2*>(&bias[col]);
                        v0 += rr.x + bb.x; v1 += rr.y + bb.y;
                    }
                    *reinterpret_cast<float2*>(&C[off]) = make_float2(v0, v1);
                }
            }
        }
}

// ---------------- sd/pd gates ----------------
__global__ __launch_bounds__(256)
void sdpd_kernel(const float* __restrict__ Nmat,
                 const float* __restrict__ Wsd, const float* __restrict__ bsd,
                 const float* __restrict__ Wpd, const float* __restrict__ bpd,
                 float* __restrict__ SDo, float* __restrict__ PDo)
{
    const int RB = 128;
    __shared__ float As[16][RB];
    __shared__ float Ws[16][16];
    int tid = threadIdx.x, row = tid & 127, cg = tid >> 7;
    int m0 = blockIdx.x * RB;
    float acc[8];
#pragma unroll
    for (int j = 0; j < 8; j++) acc[j] = 0.f;
    int wk = tid >> 4, wc = tid & 15;
    for (int k0 = 0; k0 < DMc; k0 += 16) {
#pragma unroll
        for (int r = 0; r < 2; ++r) {
            int idx = tid + r * 256, ar = idx >> 2, c4 = (idx & 3) * 4;
            float4 v = *reinterpret_cast<const float4*>(&Nmat[(size_t)(m0+ar)*DMc + k0 + c4]);
            As[c4+0][ar]=v.x; As[c4+1][ar]=v.y; As[c4+2][ar]=v.z; As[c4+3][ar]=v.w;
        }
        Ws[wk][wc] = (wc < 8) ? Wsd[(size_t)(k0+wk)*Hc + wc] : Wpd[(size_t)(k0+wk)*Hc + wc - 8];
        __syncthreads();
#pragma unroll
        for (int kk = 0; kk < 16; ++kk) {
            float a = As[kk][row];
#pragma unroll
            for (int j = 0; j < 8; j++) acc[j] += a * Ws[kk][cg*8 + j];
        }
        __syncthreads();
    }
    float* outp = cg ? PDo : SDo;
    const float* bp = cg ? bpd : bsd;
#pragma unroll
    for (int j = 0; j < 8; j++) {
        float v = acc[j] + bp[j];
        outp[(size_t)(m0+row)*Hc + j] = 1.0f / (1.0f + expf(-v));
    }
}

// ---------------- scan (8-deep prefetch, bf16 h/l out) ----------------
__global__ __launch_bounds__(256)
void scan_kernel(const float* __restrict__ Av, const float* __restrict__ Bv,
                 const float* __restrict__ QL, const float* __restrict__ QR,
                 const float* __restrict__ SDg, const float* __restrict__ PDg,
                 bf16* __restrict__ Yh, bf16* __restrict__ Yl)
{
    int blk = blockIdx.x;
    int es = blk & 1, h = (blk >> 1) & 7, b = blk >> 4;
    int e_base = es * 32;
    int tid = threadIdx.x, e_local = tid & 31, dg = tid >> 5, d0 = dg * 8;

    __shared__ float s_vec[4][64];
    __shared__ float s_state[2][64];
    __shared__ float s_red[8][32];
    __shared__ float s_sp[2];

    float pair[8];
#pragma unroll
    for (int i = 0; i < 8; i++) pair[i] = 0.f;
    if (tid < 64) { s_state[0][tid] = 0.f; s_state[1][tid] = 0.f; }

    int grp = tid >> 6, lane64 = tid & 63;
    const float* myptr = (grp == 0) ? Av : (grp == 1) ? Bv : (grp == 2) ? QL : QR;
    size_t rowbase = ((size_t)b * Tc) * INNERc + (size_t)h * SDc;
    size_t sp_base = ((size_t)b * Tc) * Hc + h;

    const int PFD = 8;
    float pf[PFD], psd[PFD], ppd[PFD];
#pragma unroll
    for (int j = 0; j < PFD; j++) {
        pf[j] = myptr[rowbase + (size_t)j * INNERc + lane64];
        if (tid == 0) {
            psd[j] = SDg[sp_base + (size_t)j * Hc];
            ppd[j] = PDg[sp_base + (size_t)j * Hc];
        }
    }

    for (int t = 0; t < Tc; t += PFD) {
#pragma unroll
        for (int j = 0; j < PFD; j++) {
            int tt = t + j, p = tt & 1;
            s_vec[grp][lane64] = pf[j];
            if (tid == 0) { s_sp[0] = psd[j]; s_sp[1] = ppd[j]; }
            __syncthreads();
            if (tt + PFD < Tc) {
                pf[j] = myptr[rowbase + (size_t)(tt + PFD) * INNERc + lane64];
                if (tid == 0) {
                    size_t sb = sp_base + (size_t)(tt + PFD) * Hc;
                    psd[j] = SDg[sb]; ppd[j] = PDg[sb];
                }
            }
            float sdv = s_sp[0], pdv = s_sp[1];
            float be = s_vec[1][e_base + e_local];
            float ompd_be = (1.f - pdv) * be;
            float qrv = s_vec[3][e_base + e_local];
            float acc = 0.f;
#pragma unroll
            for (int i = 0; i < 8; i++) {
                int d = d0 + i;
                float ps = s_state[p][d];
                pair[i] = pdv * pair[i] + ompd_be * ps;
                acc += pair[i] * s_vec[2][d];
            }
            s_red[dg][e_local] = acc;
            if (tid < 64)
                s_state[p ^ 1][tid] = sdv * s_state[p][tid] + (1.f - sdv) * s_vec[0][tid];
            __syncthreads();
            if (dg == 0) {
                float left = 0.f;
#pragma unroll
                for (int g2 = 0; g2 < 8; ++g2) left += s_red[g2][e_local];
                float v = left * qrv;
                size_t o = rowbase + (size_t)tt * INNERc + e_base + e_local;
                bf16 hv = __float2bfloat16(v);
                Yh[o] = hv;
                Yl[o] = __float2bfloat16(v - __bfloat162float(hv));
            }
        }
    }
}

// ---------------- launch ----------------
static float* symf(const void* s) { void* p = 0; cudaGetSymbolAddress(&p, s); return (float*)p; }
static bf16*  symb(const void* s) { void* p = 0; cudaGetSymbolAddress(&p, s); return (bf16*)p; }

extern "C" void kernel_launch(void* const* d_in, const int* in_sizes, int n_in,
                              void* d_out, int out_size)
{
    const float* x    = (const float*)d_in[0];
    const float* ln_g = (const float*)d_in[1];
    const float* ln_b = (const float*)d_in[2];
    const float* ffn_g= (const float*)d_in[3];
    const float* ffn_b= (const float*)d_in[4];
    const float* Wa   = (const float*)d_in[5];
    const float* Wb   = (const float*)d_in[6];
    const float* Wql  = (const float*)d_in[7];
    const float* Wqr  = (const float*)d_in[8];
    const float* Wsd  = (const float*)d_in[9];
    const float* bsd  = (const float*)d_in[10];
    const float* Wpd  = (const float*)d_in[11];
    const float* bpd  = (const float*)d_in[12];
    const float* Wout = (const float*)d_in[13];
    const float* W1   = (const float*)d_in[14];
    const float* b1   = (const float*)d_in[15];
    const float* W2   = (const float*)d_in[16];
    const float* b2   = (const float*)d_in[17];
    float* out = (float*)d_out;

    cudaFuncSetAttribute(mma_gemm<EPI_TANH>, cudaFuncAttributeMaxDynamicSharedMemorySize, SMEM_DYN);
    cudaFuncSetAttribute(mma_gemm<EPI_RES>, cudaFuncAttributeMaxDynamicSharedMemorySize, SMEM_DYN);
    cudaFuncSetAttribute(mma_gemm<EPI_GELU>, cudaFuncAttributeMaxDynamicSharedMemorySize, SMEM_DYN);
    cudaFuncSetAttribute(mma_gemm<EPI_RES_BIAS>, cudaFuncAttributeMaxDynamicSharedMemorySize, SMEM_DYN);

    dim3 tb(32, 8);
    tsplit_kernel<<<dim3(INNERc/32, DMc/32), tb>>>(Wa,  symb(g_wa_h),  symb(g_wa_l),  DMc, INNERc);
    tsplit_kernel<<<dim3(INNERc/32, DMc/32), tb>>>(Wb,  symb(g_wb_h),  symb(g_wb_l),  DMc, INNERc);
    tsplit_kernel<<<dim3(INNERc/32, DMc/32), tb>>>(Wql, symb(g_wql_h), symb(g_wql_l), DMc, INNERc);
    tsplit_kernel<<<dim3(INNERc/32, DMc/32), tb>>>(Wqr, symb(g_wqr_h), symb(g_wqr_l), DMc, INNERc);
    tsplit_kernel<<<dim3(DMc/32, INNERc/32), tb>>>(Wout, symb(g_wo_h), symb(g_wo_l), INNERc, DMc);
    tsplit_kernel<<<dim3(HIDc/32, DMc/32), tb>>>(W1, symb(g_w1_h), symb(g_w1_l), DMc, HIDc);
    tsplit_kernel<<<dim3(DMc/32, HIDc/32), tb>>>(W2, symb(g_w2_h), symb(g_w2_l), HIDc, DMc);

    ln_split_kernel<true><<<Mrows, 256>>>(x, ln_g, ln_b, symf(g_n), symb(g_nh), symb(g_nl));

    {   // projections: tanh(n @ W*) -> fp32
        dim3 grid(INNERc/128, Mrows/128);
        mma_gemm<EPI_TANH><<<grid, 256, SMEM_DYN>>>(symb(g_nh), symb(g_nl), symb(g_wa_h), symb(g_wa_l),
            symf(g_pa), nullptr, nullptr, nullptr, nullptr, Mrows, INNERc, DMc);
        mma_gemm<EPI_TANH><<<grid, 256, SMEM_DYN>>>(symb(g_nh), symb(g_nl), symb(g_wb_h), symb(g_wb_l),
            symf(g_pb), nullptr, nullptr, nullptr, nullptr, Mrows, INNERc, DMc);
        mma_gemm<EPI_TANH><<<grid, 256, SMEM_DYN>>>(symb(g_nh), symb(g_nl), symb(g_wql_h), symb(g_wql_l),
            symf(g_pql), nullptr, nullptr, nullptr, nullptr, Mrows, INNERc, DMc);
        mma_gemm<EPI_TANH><<<grid, 256, SMEM_DYN>>>(symb(g_nh), symb(g_nl), symb(g_wqr_h), symb(g_wqr_l),
            symf(g_pqr), nullptr, nullptr, nullptr, nullptr, Mrows, INNERc, DMc);
    }

    sdpd_kernel<<<Mrows/128, 256>>>(symf(g_n), Wsd, bsd, Wpd, bpd, symf(g_sd), symf(g_pd));

    scan_kernel<<<Bc*Hc*2, 256>>>(symf(g_pa), symf(g_pb), symf(g_pql), symf(g_pqr),
                                  symf(g_sd), symf(g_pd), symb(g_ysh), symb(g_ysl));

    {   // h = x + ys @ Wout
        dim3 grid(DMc/128, Mrows/128);
        mma_gemm<EPI_RES><<<grid, 256, SMEM_DYN>>>(symb(g_ysh), symb(g_ysl), symb(g_wo_h), symb(g_wo_l),
            symf(g_h), nullptr, nullptr, x, nullptr, Mrows, DMc, INNERc);
    }

    ln_split_kernel<false><<<Mrows, 256>>>(symf(g_h), ffn_g, ffn_b, nullptr, symb(g_finh), symb(g_finl));

    {   // mid = gelu(fin @ W1 + b1) -> bf16 h/l
        dim3 grid(HIDc/128, Mrows/128);
        mma_gemm<EPI_GELU><<<grid, 256, SMEM_DYN>>>(symb(g_finh), symb(g_finl), symb(g_w1_h), symb(g_w1_l),
            nullptr, symb(g_midh), symb(g_midl), nullptr, b1, Mrows, HIDc, DMc);
    }

    {   // out = h + mid @ W2 + b2
        dim3 grid(DMc/128, Mrows/128);
        mma_gemm<EPI_RES_BIAS><<<grid, 256, SMEM_DYN>>>(symb(g_midh), symb(g_midl), symb(g_w2_h), symb(g_w2_l),
            out, nullptr, nullptr, symf(g_h), b2, Mrows, DMc, HIDc);
    }
}